// round 2
// baseline (speedup 1.0000x reference)
#include <cuda_runtime.h>
#include <math_constants.h>

#define NUM_E 8192
#define DIM   512
#define BATCH 8
#define LSEQ  4096
#define NTOK  (BATCH * LSEQ)          // 32768
#define QELEMS ((size_t)BATCH * DIM * LSEQ)  // 16777216

// ---------------- scratch (device globals; no runtime allocation) ----------
__device__ float  g_xT[(size_t)NTOK * DIM];        // [N, D] token-major
__device__ float  g_codebook[(size_t)NUM_E * DIM]; // [K, D]
__device__ float  g_xnorm[NTOK];
__device__ float  g_cnorm[NUM_E];
__device__ int    g_argmin[NTOK];
__device__ double g_loss;

// ---------------------------------------------------------------------------
__global__ void zero_loss_kernel() { g_loss = 0.0; }

// inputs [B, D, L] -> g_xT [(b*L + l), d]
__global__ void transpose_kernel(const float* __restrict__ in) {
    __shared__ float tile[32][33];
    int b  = blockIdx.z;
    int d0 = blockIdx.y * 32;
    int l0 = blockIdx.x * 32;
    int tx = threadIdx.x, ty = threadIdx.y; // 32 x 8
    const float* src = in + (size_t)b * DIM * LSEQ;
#pragma unroll
    for (int i = 0; i < 4; i++)
        tile[ty + i * 8][tx] = src[(size_t)(d0 + ty + i * 8) * LSEQ + l0 + tx];
    __syncthreads();
#pragma unroll
    for (int i = 0; i < 4; i++) {
        int l = l0 + ty + i * 8;
        g_xT[(size_t)(b * LSEQ + l) * DIM + d0 + tx] = tile[tx][ty + i * 8];
    }
}

// codebook[k][d] = sum_j emb[k][j] * proj[d][j]   (Linear: emb @ proj.T)
__global__ __launch_bounds__(256) void codebook_gemm_kernel(
    const float* __restrict__ E, const float* __restrict__ P) {
    __shared__ float Es[16][65];
    __shared__ float Ps[16][65];
    int tid = threadIdx.x;
    int ty = tid >> 4, tx = tid & 15;
    int k0 = blockIdx.y * 64;
    int d0 = blockIdx.x * 64;
    float acc[4][4];
#pragma unroll
    for (int i = 0; i < 4; i++)
#pragma unroll
        for (int j = 0; j < 4; j++) acc[i][j] = 0.f;

    for (int j0 = 0; j0 < DIM; j0 += 16) {
#pragma unroll
        for (int i = 0; i < 4; i++) {
            int e = tid + i * 256;
            int m = e >> 4, j = e & 15;
            Es[j][m] = E[(size_t)(k0 + m) * DIM + j0 + j];
            Ps[j][m] = P[(size_t)(d0 + m) * DIM + j0 + j];
        }
        __syncthreads();
#pragma unroll
        for (int j = 0; j < 16; j++) {
            float a[4], bb[4];
#pragma unroll
            for (int i = 0; i < 4; i++) a[i] = Es[j][ty * 4 + i];
#pragma unroll
            for (int i = 0; i < 4; i++) bb[i] = Ps[j][tx * 4 + i];
#pragma unroll
            for (int i = 0; i < 4; i++)
#pragma unroll
                for (int jj = 0; jj < 4; jj++) acc[i][jj] += a[i] * bb[jj];
        }
        __syncthreads();
    }
#pragma unroll
    for (int i = 0; i < 4; i++)
#pragma unroll
        for (int jj = 0; jj < 4; jj++)
            g_codebook[(size_t)(k0 + ty * 4 + i) * DIM + d0 + tx * 4 + jj] = acc[i][jj];
}

// which=0: xnorm over g_xT (NTOK rows); which=1: cnorm over g_codebook (NUM_E rows)
__global__ void rownorm_kernel(int which) {
    int warp = (blockIdx.x * blockDim.x + threadIdx.x) >> 5;
    int lane = threadIdx.x & 31;
    int rows = which ? NUM_E : NTOK;
    if (warp >= rows) return;
    const float* r = (which ? g_codebook : g_xT) + (size_t)warp * DIM;
    float s = 0.f;
#pragma unroll
    for (int i = 0; i < DIM / 32; i++) { float v = r[lane + i * 32]; s += v * v; }
#pragma unroll
    for (int o = 16; o; o >>= 1) s += __shfl_down_sync(0xffffffffu, s, o);
    if (lane == 0) (which ? g_cnorm : g_xnorm)[warp] = s;
}

// Fused distance GEMM + argmin.  BM=128 tokens x BN=128 codes x BK=8, 8x8/thread.
__global__ __launch_bounds__(256, 2) void distance_argmin_kernel() {
    __shared__ float Xs[8][128];
    __shared__ float Cs[8][128];
    __shared__ float cns[128];
    __shared__ float rv[128][17];
    __shared__ int   ri[128][17];

    int tid = threadIdx.x;
    int ty = tid >> 4, tx = tid & 15;
    int m0 = blockIdx.x * 128;

    // staging assignment: 256 threads * 4 float2 loads cover 128 rows x 8 cols
    // for each of X and C.  thread covers row rj = tid>>2 + 64*i, cols (tid&3)*2.
    int srow = tid >> 2;
    int scol = (tid & 3) * 2;

    float xn[8], best[8];
    int   bidx[8];
#pragma unroll
    for (int i = 0; i < 8; i++) {
        xn[i]   = g_xnorm[m0 + ty * 8 + i];
        best[i] = CUDART_INF_F;
        bidx[i] = 0;
    }

    for (int k0 = 0; k0 < NUM_E; k0 += 128) {
        if (tid < 128) cns[tid] = g_cnorm[k0 + tid];
        float acc[8][8];
#pragma unroll
        for (int i = 0; i < 8; i++)
#pragma unroll
            for (int j = 0; j < 8; j++) acc[i][j] = 0.f;

        for (int d0 = 0; d0 < DIM; d0 += 8) {
#pragma unroll
            for (int i = 0; i < 2; i++) {
                int m = srow + i * 64;
                float2 xv = *(const float2*)&g_xT[(size_t)(m0 + m) * DIM + d0 + scol];
                float2 cv = *(const float2*)&g_codebook[(size_t)(k0 + m) * DIM + d0 + scol];
                Xs[scol][m]     = xv.x;
                Xs[scol + 1][m] = xv.y;
                Cs[scol][m]     = cv.x;
                Cs[scol + 1][m] = cv.y;
            }
            __syncthreads();
#pragma unroll
            for (int j = 0; j < 8; j++) {
                float a[8], bb[8];
#pragma unroll
                for (int i = 0; i < 8; i++) a[i]  = Xs[j][ty * 8 + i];
#pragma unroll
                for (int i = 0; i < 8; i++) bb[i] = Cs[j][tx * 8 + i];
#pragma unroll
                for (int i = 0; i < 8; i++)
#pragma unroll
                    for (int jj = 0; jj < 8; jj++) acc[i][jj] += a[i] * bb[jj];
            }
            __syncthreads();
        }
        // epilogue: exact reference expression, ascending index, strict < keeps first-min
#pragma unroll
        for (int jj = 0; jj < 8; jj++) {
            float cn = cns[tx * 8 + jj];
            int   kk = k0 + tx * 8 + jj;
#pragma unroll
            for (int i = 0; i < 8; i++) {
                float dv = (xn[i] + cn) - 2.0f * acc[i][jj];
                if (dv < best[i]) { best[i] = dv; bidx[i] = kk; }
            }
        }
        __syncthreads();  // protect cns for next iteration
    }

#pragma unroll
    for (int i = 0; i < 8; i++) {
        rv[ty * 8 + i][tx] = best[i];
        ri[ty * 8 + i][tx] = bidx[i];
    }
    __syncthreads();
    if (tid < 128) {
        float bv = rv[tid][0];
        int   bi = ri[tid][0];
#pragma unroll
        for (int t = 1; t < 16; t++) {
            float v = rv[tid][t]; int ii = ri[tid][t];
            if (v < bv || (v == bv && ii < bi)) { bv = v; bi = ii; }
        }
        g_argmin[m0 + tid] = bi;
    }
}

// gather codebook rows, write quantized [B,D,L], indices-as-float, accumulate loss
__global__ __launch_bounds__(256) void gather_out_kernel(
    const float* __restrict__ in, float* __restrict__ out) {
    __shared__ float qs[16][513];
    __shared__ int sidx[16];
    __shared__ double wsum[8];
    int t0 = blockIdx.x * 16;
    int tid = threadIdx.x;
    if (tid < 16) sidx[tid] = g_argmin[t0 + tid];
    __syncthreads();
    // 16 tokens x 512 d = 8192 floats = 2048 float4; 256 threads x 8 iters
#pragma unroll
    for (int i = 0; i < 8; i++) {
        int e = tid + i * 256;          // float4 index
        int tok = e >> 7, d4 = e & 127; // 128 float4 per row
        float4 v = *(const float4*)&g_codebook[(size_t)sidx[tok] * DIM + d4 * 4];
        qs[tok][d4 * 4]     = v.x;
        qs[tok][d4 * 4 + 1] = v.y;
        qs[tok][d4 * 4 + 2] = v.z;
        qs[tok][d4 * 4 + 3] = v.w;
    }
    __syncthreads();
    int b  = t0 / LSEQ;
    int l0 = t0 % LSEQ;
    const float* src = in  + (size_t)b * DIM * LSEQ;
    float*       dst = out + (size_t)b * DIM * LSEQ;
    double ls = 0.0;
#pragma unroll
    for (int i = 0; i < 32; i++) {
        int e = tid + i * 256;
        int d = e >> 4, l = e & 15;
        float q = qs[l][d];
        float x = src[(size_t)d * LSEQ + l0 + l];
        float dd = q - x;                 // stop_grad(quantized - x), forward value
        dst[(size_t)d * LSEQ + l0 + l] = x + dd;   // straight-through forward
        ls += (double)dd * (double)dd;
    }
    if (tid < 16) out[QELEMS + 1 + (size_t)(t0 + tid)] = (float)sidx[tid];
#pragma unroll
    for (int o = 16; o; o >>= 1) ls += __shfl_down_sync(0xffffffffu, ls, o);
    if ((tid & 31) == 0) wsum[tid >> 5] = ls;
    __syncthreads();
    if (tid == 0) {
        double s = 0.0;
#pragma unroll
        for (int w = 0; w < 8; w++) s += wsum[w];
        atomicAdd(&g_loss, s);
    }
}

__global__ void loss_final_kernel(float* __restrict__ out) {
    // loss = q_latent + 0.25 * e_latent; forward both equal MSE(q, x)
    out[QELEMS] = (float)(1.25 * g_loss / (double)QELEMS);
}

// ---------------------------------------------------------------------------
extern "C" void kernel_launch(void* const* d_in, const int* in_sizes, int n_in,
                              void* d_out, int out_size) {
    const float* inputs = (const float*)d_in[0];
    const float* emb    = (const float*)d_in[1];
    const float* proj   = (const float*)d_in[2];
    float* out = (float*)d_out;

    zero_loss_kernel<<<1, 1>>>();
    transpose_kernel<<<dim3(LSEQ / 32, DIM / 32, BATCH), dim3(32, 8)>>>(inputs);
    codebook_gemm_kernel<<<dim3(DIM / 64, NUM_E / 64), 256>>>(emb, proj);
    rownorm_kernel<<<(NTOK * 32) / 256, 256>>>(0);   // xnorm
    rownorm_kernel<<<(NUM_E * 32) / 256, 256>>>(1);  // cnorm
    distance_argmin_kernel<<<NTOK / 128, 256>>>();
    gather_out_kernel<<<NTOK / 16, 256>>>(inputs, out);
    loss_final_kernel<<<1, 1>>>(out);
}